// round 5
// baseline (speedup 1.0000x reference)
#include <cuda_runtime.h>

#define BB 32
#define FF 35
#define SS 80
#define NC (2*FF+1)          // 71
#define NPAIR (BB*FF)        // 1120 chains
#define NW (NPAIR/2)         // 560 warps (2 chains per warp, packed f32x2)
#define WPB 8                // warps per block -> 2 per SMSP
#define NB (NW/WPB)          // 70 blocks
#define LN2F 0.69314718055994530942f

typedef unsigned long long u64;

__device__ float g_loss[NPAIR];
__device__ unsigned g_count = 0;

__device__ __forceinline__ u64 pk2(float x, float y) {
    u64 r; asm("mov.b64 %0, {%1,%2};" : "=l"(r) : "f"(x), "f"(y)); return r;
}
__device__ __forceinline__ void up2(u64 v, float& x, float& y) {
    asm("mov.b64 {%0,%1}, %2;" : "=f"(x), "=f"(y) : "l"(v));
}
__device__ __forceinline__ u64 add2(u64 a, u64 b) {
    u64 r; asm("add.rn.f32x2 %0, %1, %2;" : "=l"(r) : "l"(a), "l"(b)); return r;
}
__device__ __forceinline__ u64 mul2(u64 a, u64 b) {
    u64 r; asm("mul.rn.f32x2 %0, %1, %2;" : "=l"(r) : "l"(a), "l"(b)); return r;
}
__device__ __forceinline__ u64 fma2_(u64 a, u64 b, u64 c) {
    u64 r; asm("fma.rn.f32x2 %0, %1, %2, %3;" : "=l"(r) : "l"(a), "l"(b), "l"(c)); return r;
}
__device__ __forceinline__ float frcp(float x) {
    float r; asm("rcp.approx.f32 %0, %1;" : "=f"(r) : "f"(x)); return r;
}

#define EXTR(Z, ez) { int _bt = __float_as_int(Z); ez += (_bt >> 23) - 127; \
                      Z = __int_as_float((_bt & 0x7fffff) | 0x3f800000); }

__global__ __launch_bounds__(256, 1)
void ctc_fwd(const float* __restrict__ logits,
             const int*   __restrict__ targets,
             const int*   __restrict__ in_len,
             const int*   __restrict__ tgt_len,
             int T, float* __restrict__ out)
{
    __shared__ ulonglong2 sEE[WPB][32];   // per step: (e0'A,e0'B), (pd'A,pd'B)
    __shared__ float      sred[256];
    __shared__ int        sflag;

    const unsigned FM = 0xffffffffu;
    const int widb = threadIdx.x >> 5;
    const int lane = threadIdx.x & 31;
    const int gw = blockIdx.x * WPB + widb;    // 0..559

    const int cA = gw * 2, cB = cA + 1;
    const int bA = cA / FF, fA = cA - bA * FF;
    const int bB = cB / FF, fB = cB - bB * FF;
    const int tlA = tgt_len[cA], tlB = tgt_len[cB];
    const int LvA = 2 * tlA + 1, LvB = 2 * tlB + 1;
    int TinA = in_len[bA]; if (TinA > T) TinA = T;
    int TinB = in_len[bB]; if (TinB > T) TinB = T;
    const int Tmin = (TinA < TinB) ? TinA : TinB;
    const int Tmax = (TinA > TinB) ? TinA : TinB;

    const int l0 = lane * 6;
    const int* tgA = targets + (size_t)cA * SS;
    const int* tgB = targets + (size_t)cB * SS;

    u64 M[6], W[3], SK[3];
    #pragma unroll
    for (int j = 0; j < 6; j++)
        M[j] = pk2((l0 + j < LvA) ? 1.f : 0.f, (l0 + j < LvB) ? 1.f : 0.f);
    #pragma unroll
    for (int j = 0; j < 3; j++) {
        int l = l0 + 2 * j + 1;
        float wa = 0.f, ska = 0.f, wb = 0.f, skb = 0.f;
        if (l < LvA) { int s = (l - 1) >> 1; int tv = tgA[s];
            wa = (float)tv; ska = (l >= 3 && tgA[s - 1] != tv) ? 1.f : 0.f; }
        if (l < LvB) { int s = (l - 1) >> 1; int tv = tgB[s];
            wb = (float)tv; skb = (l >= 3 && tgB[s - 1] != tv) ? 1.f : 0.f; }
        W[j] = pk2(wa, wb); SK[j] = pk2(ska, skb);
    }

    const float* pA = logits + (size_t)bA * NC + fA;
    const float* pB = logits + (size_t)bB * NC + fB;
    const int oblA = 2 * FF - fA;
    const int oblB = 2 * FF - fB;
    const int TS = BB * NC;

    u64 A0 = 0, A1 = 0, A2 = 0, A3 = 0, A4 = 0, A5 = 0, a5p = 0;
    float ZaccA = 1.f, ZaccB = 1.f, PaccA = 1.f, PaccB = 1.f;
    int ezA = 0, ezB = 0, epA = 0, epB = 0, EA = 0, EB = 0;

    // ---- t = 0 init ----
    {
        float e0a = __expf(pA[0]), e1a = __expf(pA[FF]), e2a = __expf(pA[oblA]);
        float e0b = __expf(pB[0]), e1b = __expf(pB[FF]), e2b = __expf(pB[oblB]);
        if (lane == 0) {
            A0 = pk2(e2a, e2b);
            A1 = mul2(fma2_(W[0], pk2(e1a - e0a, e1b - e0b), pk2(e0a, e0b)), M[1]);
            ZaccA = e0a + e1a + e2a;
            ZaccB = e0b + e1b + e2b;
        }
    }

    // ---- prefetch first block (t = 1 + lane) ----
    float rpA = 0.f, rnA = 0.f, rbA = 0.f, rpB = 0.f, rnB = 0.f, rbB = 0.f;
    {
        int tt = 1 + lane;
        if (tt < Tmax) {
            const float* qa = pA + (size_t)tt * TS;
            rpA = qa[0]; rnA = qa[FF]; rbA = qa[oblA];
            const float* qb = pB + (size_t)tt * TS;
            rpB = qb[0]; rnB = qb[FF]; rbB = qb[oblB];
        }
    }

// one CTC step from a pre-loaded emission register pair `ep`
#define STEP_EP(ep) { \
    u64 t1 = fma2_(W[0], ep.y, ep.x); \
    u64 t3 = fma2_(W[1], ep.y, ep.x); \
    u64 t5 = fma2_(W[2], ep.y, ep.x); \
    u64 n0 = add2(A0, a5p); \
    u64 n1 = mul2(fma2_(SK[0], a5p, add2(A1, A0)), t1); \
    u64 n2 = add2(A2, A1); \
    u64 n3 = mul2(fma2_(SK[1], A1, add2(A3, A2)), t3); \
    u64 n4 = add2(A4, A3); \
    u64 n5 = mul2(fma2_(SK[2], A3, add2(A5, A4)), t5); \
    A0 = n0; A1 = n1; A2 = n2; A3 = n3; A4 = n4; A5 = n5; \
    a5p = __shfl_up_sync(FM, A5, 1); \
    a5p = lane ? a5p : 0ull; }

#define APPLY(sv) { \
    float sa, sb; up2(sv, sa, sb); \
    int exa = (__float_as_int(sa) >> 23) & 0xff; \
    int exb = (__float_as_int(sb) >> 23) & 0xff; \
    exa = min(max(exa, 1), 253); exb = min(max(exb, 1), 253); \
    EA += exa - 127; EB += exb - 127; \
    u64 sc = pk2(__int_as_float((254 - exa) << 23), __int_as_float((254 - exb) << 23)); \
    A0 = mul2(A0, mul2(sc, M[0])); A1 = mul2(A1, mul2(sc, M[1])); \
    A2 = mul2(A2, mul2(sc, M[2])); A3 = mul2(A3, mul2(sc, M[3])); \
    A4 = mul2(A4, mul2(sc, M[4])); A5 = mul2(A5, mul2(sc, M[5])); \
    a5p = __shfl_up_sync(FM, A5, 1); \
    a5p = lane ? a5p : 0ull; }

    for (int tb = 1; tb < Tmax; tb += 32) {
        int ns = Tmax - tb; if (ns > 32) ns = 32;

        // ---- stage blank-factored emissions; accumulate Z and blank product P ----
        float e0a = __expf(rpA), e1a = __expf(rnA), e2a = __expf(rbA);
        float e0b = __expf(rpB), e1b = __expf(rnB), e2b = __expf(rbB);
        float r2a = frcp(e2a), r2b = frcp(e2b);
        __syncwarp();
        sEE[widb][lane] = make_ulonglong2(pk2(e0a * r2a, e0b * r2b),
                                          pk2((e1a - e0a) * r2a, (e1b - e0b) * r2b));
        int tt = tb + lane;
        if (tt < TinA) { ZaccA *= (e0a + e1a + e2a); EXTR(ZaccA, ezA);
                         PaccA *= e2a;               EXTR(PaccA, epA); }
        if (tt < TinB) { ZaccB *= (e0b + e1b + e2b); EXTR(ZaccB, ezB);
                         PaccB *= e2b;               EXTR(PaccB, epB); }

        // prefetch next block
        int tn = tb + 32 + lane;
        if (tn < Tmax) {
            const float* qa = pA + (size_t)tn * TS;
            rpA = qa[0]; rnA = qa[FF]; rbA = qa[oblA];
            const float* qb = pB + (size_t)tn * TS;
            rpB = qb[0]; rnB = qb[FF]; rbB = qb[oblB];
        }
        __syncwarp();

        if (tb + 32 <= Tmin) {
            // fast path: LDS software-pipelined one step ahead;
            // rescale every 16 steps, butterfly spread over steps 11..15 / 27..31
            u64 sv = 0;
            ulonglong2 ep = sEE[widb][0];
            #pragma unroll
            for (int i = 0; i < 32; i++) {
                ulonglong2 epn;
                if (i < 31) epn = sEE[widb][i + 1];
                STEP_EP(ep);
                if (i < 31) ep = epn;
                if (i == 10 || i == 26)
                    sv = add2(add2(add2(A0, A1), add2(A2, A3)), add2(A4, A5));
                if (i == 11 || i == 27) sv = add2(sv, __shfl_xor_sync(FM, sv, 1));
                if (i == 12 || i == 28) sv = add2(sv, __shfl_xor_sync(FM, sv, 2));
                if (i == 13 || i == 29) sv = add2(sv, __shfl_xor_sync(FM, sv, 4));
                if (i == 14 || i == 30) sv = add2(sv, __shfl_xor_sync(FM, sv, 8));
                if (i == 15 || i == 31) {
                    sv = add2(sv, __shfl_xor_sync(FM, sv, 16));
                    APPLY(sv);
                }
            }
        } else {
            // tail / unequal-length path
            for (int i = 0; i < ns; i++) {
                int t = tb + i;
                u64 o0 = A0, o1 = A1, o2 = A2, o3 = A3, o4 = A4, o5 = A5;
                ulonglong2 ep = sEE[widb][i];
                STEP_EP(ep);
                bool ga = (t < TinA), gb = (t < TinB);
                if (!(ga && gb)) {
                    float nx, ny, ox, oy;
                    #define SELST(N, O) { up2(N, nx, ny); up2(O, ox, oy); \
                        N = pk2(ga ? nx : ox, gb ? ny : oy); }
                    SELST(A0, o0) SELST(A1, o1) SELST(A2, o2)
                    SELST(A3, o3) SELST(A4, o4) SELST(A5, o5)
                    #undef SELST
                    a5p = __shfl_up_sync(FM, A5, 1);
                    a5p = lane ? a5p : 0ull;
                }
                if ((i & 7) == 7) {
                    u64 sv = add2(add2(add2(A0, A1), add2(A2, A3)), add2(A4, A5));
                    #pragma unroll
                    for (int o = 16; o; o >>= 1)
                        sv = add2(sv, __shfl_xor_sync(FM, sv, o));
                    APPLY(sv);
                }
            }
        }
    }

    // ---- final gather: alpha[2*tl] + alpha[2*tl-1] per chain ----
    float lastA = 0.f, prvA = 0.f, lastB = 0.f, prvB = 0.f;
    {
        int ilA = 2 * tlA, ilB = 2 * tlB;
        float x, y;
        #define GATH(j, R) { up2(R, x, y); int l = l0 + j; \
            if (l == ilA) lastA = x; if (l == ilA - 1) prvA = x; \
            if (l == ilB) lastB = y; if (l == ilB - 1) prvB = y; }
        GATH(0, A0) GATH(1, A1) GATH(2, A2) GATH(3, A3) GATH(4, A4) GATH(5, A5)
        #undef GATH
    }
    u64 fs = pk2(lastA + prvA, lastB + prvB);
    u64 lz = pk2(__logf(ZaccA) - __logf(PaccA) + (float)(ezA - epA) * LN2F,
                 __logf(ZaccB) - __logf(PaccB) + (float)(ezB - epB) * LN2F);
    #pragma unroll
    for (int o = 16; o; o >>= 1) {
        fs = add2(fs, __shfl_xor_sync(FM, fs, o));
        lz = add2(lz, __shfl_xor_sync(FM, lz, o));
    }
    if (lane == 0) {
        float sa, sb, za, zb;
        up2(fs, sa, sb); up2(lz, za, zb);
        float lossA = 0.f, lossB = 0.f;
        if (sa > 0.f) lossA = za - (__logf(sa) + (float)EA * LN2F);
        if (sb > 0.f) lossB = zb - (__logf(sb) + (float)EB * LN2F);
        g_loss[cA] = lossA / fmaxf((float)tlA, 1.f);
        g_loss[cB] = lossB / fmaxf((float)tlB, 1.f);
    }

    // ---- fused grid reduction ----
    __syncthreads();
    if (threadIdx.x == 0) {
        __threadfence();
        unsigned v = atomicAdd(&g_count, 1u);
        sflag = (v == gridDim.x - 1u) ? 1 : 0;
    }
    __syncthreads();
    if (sflag) {
        __threadfence();
        float acc = 0.f;
        for (int i = threadIdx.x; i < NPAIR; i += 256) acc += g_loss[i];
        sred[threadIdx.x] = acc;
        __syncthreads();
        #pragma unroll
        for (int o = 128; o; o >>= 1) {
            if (threadIdx.x < o) sred[threadIdx.x] += sred[threadIdx.x + o];
            __syncthreads();
        }
        if (threadIdx.x == 0) {
            out[0] = sred[0] * (1.0f / (float)BB);
            g_count = 0;
            __threadfence();
        }
    }
}

extern "C" void kernel_launch(void* const* d_in, const int* in_sizes, int n_in,
                              void* d_out, int out_size)
{
    const float* logits  = (const float*)d_in[0];
    const int*   targets = (const int*)d_in[1];
    const int*   in_len  = (const int*)d_in[2];
    const int*   tgt_len = (const int*)d_in[3];
    float* out = (float*)d_out;

    int T = in_sizes[0] / (BB * NC);   // 600

    // 70 blocks x 256 threads: 8 warps/SM -> 2 warps per SMSP (latency hiding)
    ctc_fwd<<<NB, 256>>>(logits, targets, in_len, tgt_len, T, out);
}

// round 6
// speedup vs baseline: 1.6201x; 1.6201x over previous
#include <cuda_runtime.h>

#define BB 32
#define FF 35
#define SS 80
#define NC (2*FF+1)          // 71
#define NPAIR (BB*FF)        // 1120 chains, 1 chain per warp
#define WPB 8                // 8 warps per block -> 2 per SMSP
#define NB (NPAIR/WPB)       // 140 blocks
#define LN2F 0.69314718055994530942f

__device__ float g_loss[NPAIR];
__device__ unsigned g_count = 0;

__device__ __forceinline__ float frcp(float x) {
    float r; asm("rcp.approx.f32 %0, %1;" : "=f"(r) : "f"(x)); return r;
}

// mantissa-normalize into [1,2), accumulate exponent
#define EXTR(Z, ez) { int _bt = __float_as_int(Z); ez += (_bt >> 23) - 127; \
                      Z = __int_as_float((_bt & 0x7fffff) | 0x3f800000); }

__global__ __launch_bounds__(256, 1)
void ctc_fwd(const float* __restrict__ logits,
             const int*   __restrict__ targets,
             const int*   __restrict__ in_len,
             const int*   __restrict__ tgt_len,
             int T, float* __restrict__ out)
{
    __shared__ float2 sEE[WPB][32];    // per step: (e0', e1') blank-factored
    __shared__ float  sred[256];
    __shared__ int    sflag;

    const unsigned FM = 0xffffffffu;
    const int widb = threadIdx.x >> 5;
    const int lane = threadIdx.x & 31;
    const int c = blockIdx.x * WPB + widb;    // chain 0..1119

    const int b = c / FF, f = c - b * FF;
    const int tl = tgt_len[c];
    const int Lv = 2 * tl + 1;
    int Tin = in_len[b]; if (Tin > T) Tin = T;

    const int l0 = lane * 6;
    const int* tg = targets + (size_t)c * SS;

    // per-lane constants
    const float M0 = (l0 + 0 < Lv) ? 1.f : 0.f;
    const float M1 = (l0 + 1 < Lv) ? 1.f : 0.f;
    const float M2 = (l0 + 2 < Lv) ? 1.f : 0.f;
    const float M3 = (l0 + 3 < Lv) ? 1.f : 0.f;
    const float M4 = (l0 + 4 < Lv) ? 1.f : 0.f;
    const float M5 = (l0 + 5 < Lv) ? 1.f : 0.f;
    bool  w1 = false, w3 = false, w5 = false;
    float sk1 = 0.f, sk3 = 0.f, sk5 = 0.f;
    {
        int l = l0 + 1;
        if (l < Lv) { int s = (l - 1) >> 1; int tv = tg[s];
            w1 = (tv != 0); sk1 = (l >= 3 && tg[s - 1] != tv) ? 1.f : 0.f; }
        l = l0 + 3;
        if (l < Lv) { int s = (l - 1) >> 1; int tv = tg[s];
            w3 = (tv != 0); sk3 = (l >= 3 && tg[s - 1] != tv) ? 1.f : 0.f; }
        l = l0 + 5;
        if (l < Lv) { int s = (l - 1) >> 1; int tv = tg[s];
            w5 = (tv != 0); sk5 = (l >= 3 && tg[s - 1] != tv) ? 1.f : 0.f; }
    }
    const float lzm = lane ? 1.f : 0.f;   // zeroes a5p on lane 0

    const float* pC = logits + (size_t)b * NC + f;   // chain's pos channel, t=0
    const int obl = 2 * FF - f;                      // pos -> blank offset
    const int TS = BB * NC;

    float A0 = 0.f, A1 = 0.f, A2 = 0.f, A3 = 0.f, A4 = 0.f, A5 = 0.f, a5p = 0.f;
    float Zacc = 1.f, Pacc = 1.f;
    int ez = 0, ep_ = 0, E = 0;

    // ---- t = 0 init (full emissions; Z(0) folded into lane-0 Zacc) ----
    {
        float e0 = __expf(pC[0]), e1 = __expf(pC[FF]), e2 = __expf(pC[obl]);
        if (lane == 0) {
            A0 = e2;
            A1 = (w1 ? e1 : e0) * M1;
            Zacc = e0 + e1 + e2;
        }
    }

    // ---- prefetch first block (t = 1 + lane) ----
    float rp = 0.f, rn = 0.f, rb = 0.f;
    {
        int tt = 1 + lane;
        if (tt < Tin) {
            const float* q = pC + (size_t)tt * TS;
            rp = q[0]; rn = q[FF]; rb = q[obl];
        }
    }

// one CTC step from pre-loaded blank-factored emissions (e0', e1')
#define STEP_EP(e0v, e1v) { \
    float t1v = w1 ? e1v : e0v; \
    float t3v = w3 ? e1v : e0v; \
    float t5v = w5 ? e1v : e0v; \
    float n5 = fmaf(sk5, A3, A5 + A4) * t5v; \
    float n0 = fmaf(lzm, a5p, A0); \
    float n1 = fmaf(sk1, a5p, A1 + A0) * t1v; \
    float n2 = A2 + A1; \
    float n3 = fmaf(sk3, A1, A3 + A2) * t3v; \
    float n4 = A4 + A3; \
    A0 = n0; A1 = n1; A2 = n2; A3 = n3; A4 = n4; A5 = n5; \
    a5p = __shfl_up_sync(FM, A5, 1); }

// exact power-of-2 rescale from reduced sum sv; masks folded in; a5p refreshed
#define APPLY(sv) { \
    int ex = (__float_as_int(sv) >> 23) & 0xff; \
    ex = min(max(ex, 1), 253); \
    E += ex - 127; \
    float sc = __int_as_float((254 - ex) << 23); \
    A0 = A0 * (sc * M0); A1 = A1 * (sc * M1); A2 = A2 * (sc * M2); \
    A3 = A3 * (sc * M3); A4 = A4 * (sc * M4); A5 = A5 * (sc * M5); \
    a5p = __shfl_up_sync(FM, A5, 1); }

    for (int tb = 1; tb < Tin; tb += 32) {
        int ns = Tin - tb; if (ns > 32) ns = 32;

        // ---- stage blank-factored emissions; accumulate Z and blank product P ----
        float e0 = __expf(rp), e1 = __expf(rn), e2 = __expf(rb);
        float r2 = frcp(e2);
        __syncwarp();
        sEE[widb][lane] = make_float2(e0 * r2, e1 * r2);
        int tt = tb + lane;
        if (tt < Tin) {
            Zacc *= (e0 + e1 + e2); EXTR(Zacc, ez);
            Pacc *= e2;             EXTR(Pacc, ep_);
        }
        // prefetch next block
        int tn = tb + 32 + lane;
        if (tn < Tin) {
            const float* q = pC + (size_t)tn * TS;
            rp = q[0]; rn = q[FF]; rb = q[obl];
        }
        __syncwarp();

        if (ns == 32) {
            // fast path: LDS pipelined one step ahead;
            // rescale every 16 steps, butterfly spread over steps 11..15 / 27..31
            float sv = 0.f;
            float2 ep = sEE[widb][0];
            #pragma unroll
            for (int i = 0; i < 32; i++) {
                float2 epn;
                if (i < 31) epn = sEE[widb][i + 1];
                STEP_EP(ep.x, ep.y);
                if (i < 31) ep = epn;
                if (i == 10 || i == 26)
                    sv = ((A0 + A1) + (A2 + A3)) + (A4 + A5);
                if (i == 11 || i == 27) sv += __shfl_xor_sync(FM, sv, 1);
                if (i == 12 || i == 28) sv += __shfl_xor_sync(FM, sv, 2);
                if (i == 13 || i == 29) sv += __shfl_xor_sync(FM, sv, 4);
                if (i == 14 || i == 30) sv += __shfl_xor_sync(FM, sv, 8);
                if (i == 15 || i == 31) {
                    sv += __shfl_xor_sync(FM, sv, 16);
                    APPLY(sv);
                }
            }
        } else {
            // tail: single chain, loop just ends at Tin
            for (int i = 0; i < ns; i++) {
                float2 ep = sEE[widb][i];
                STEP_EP(ep.x, ep.y);
                if ((i & 7) == 7) {
                    float sv = ((A0 + A1) + (A2 + A3)) + (A4 + A5);
                    #pragma unroll
                    for (int o = 16; o; o >>= 1)
                        sv += __shfl_xor_sync(FM, sv, o);
                    APPLY(sv);
                }
            }
        }
    }

    // ---- final gather: alpha[2*tl] + alpha[2*tl-1] ----
    float last = 0.f, prv = 0.f;
    {
        int il = 2 * tl;
        #define GATH(j, R) { int l = l0 + j; \
            if (l == il) last = R; if (l == il - 1) prv = R; }
        GATH(0, A0) GATH(1, A1) GATH(2, A2)
        GATH(3, A3) GATH(4, A4) GATH(5, A5)
        #undef GATH
    }
    float fs = last + prv;
    float lz = __logf(Zacc) - __logf(Pacc) + (float)(ez - ep_) * LN2F;
    #pragma unroll
    for (int o = 16; o; o >>= 1) {
        fs += __shfl_xor_sync(FM, fs, o);
        lz += __shfl_xor_sync(FM, lz, o);
    }
    if (lane == 0) {
        float lossv = 0.f;
        if (fs > 0.f) lossv = lz - (__logf(fs) + (float)E * LN2F);
        g_loss[c] = lossv / fmaxf((float)tl, 1.f);
    }

    // ---- fused grid reduction: last-arriving block sums g_loss ----
    __syncthreads();
    if (threadIdx.x == 0) {
        __threadfence();
        unsigned v = atomicAdd(&g_count, 1u);
        sflag = (v == gridDim.x - 1u) ? 1 : 0;
    }
    __syncthreads();
    if (sflag) {
        __threadfence();
        float acc = 0.f;
        for (int i = threadIdx.x; i < NPAIR; i += 256) acc += g_loss[i];
        sred[threadIdx.x] = acc;
        __syncthreads();
        #pragma unroll
        for (int o = 128; o; o >>= 1) {
            if (threadIdx.x < o) sred[threadIdx.x] += sred[threadIdx.x + o];
            __syncthreads();
        }
        if (threadIdx.x == 0) {
            out[0] = sred[0] * (1.0f / (float)BB);
            g_count = 0;
            __threadfence();
        }
    }
}

extern "C" void kernel_launch(void* const* d_in, const int* in_sizes, int n_in,
                              void* d_out, int out_size)
{
    const float* logits  = (const float*)d_in[0];
    const int*   targets = (const int*)d_in[1];
    const int*   in_len  = (const int*)d_in[2];
    const int*   tgt_len = (const int*)d_in[3];
    float* out = (float*)d_out;

    int T = in_sizes[0] / (BB * NC);   // 600

    // 140 blocks x 256 threads: 1120 warps, 1 chain each, 2 warps per SMSP on 140 SMs
    ctc_fwd<<<NB, 256>>>(logits, targets, in_len, tgt_len, T, out);
}